// round 15
// baseline (speedup 1.0000x reference)
#include <cuda_runtime.h>
#include <math.h>
#include <stdint.h>

// Problem constants
#define NLAT 361
#define NLON 720
#define MMAX 361
#define LMAX 360
#define BC   128
#define NROWS (BC * NLAT)   // 46208

#define X_ELEMS  (BC * NLAT * NLON)
#define W_ELEMS  (MMAX * LMAX * NLAT)
#define OUT_REAL (BC * LMAX * MMAX)

#define K1P 368             // latitude K padded (stage-2)
#define K2P 192             // folded DFT K padded (stage-1)
#define NT1 (K2P / 16)      // 12
#define NT2 (K1P / 16)      // 23
#define LPAD 384
#define SPITCH 132          // stage-1 smem pitch ([k][r] layout)
#define APITCH 20           // stage-2 smem pitch ([row][k] layout; 16+4 window)

// -------- static device scratch (zero-initialized at load) --------
__device__ float sht_te[K2P * K2P];
__device__ float sht_to[K2P * K2P];
__device__ float sht_ye[(size_t)K2P * NROWS];
__device__ float sht_yo[(size_t)K2P * NROWS];
__device__ float sht_xfr[(size_t)MMAX * BC * K1P]; // [m][bc][k], tf32-rounded, k-pad zero
__device__ float sht_s2[(size_t)MMAX * BC * LPAD]; // [m][bc][l]

#define CP_ASYNC16(s, g) asm volatile("cp.async.ca.shared.global [%0], [%1], 16;" :: "r"(s), "l"(g) : "memory")
#define CP_ASYNC4(s, g)  asm volatile("cp.async.ca.shared.global [%0], [%1], 4;"  :: "r"(s), "l"(g) : "memory")
#define CP_COMMIT()      asm volatile("cp.async.commit_group;" ::: "memory")
#define CP_WAIT1()       asm volatile("cp.async.wait_group 1;" ::: "memory")
#define CP_WAIT0()       asm volatile("cp.async.wait_group 0;" ::: "memory")

__device__ __forceinline__ float tf32_round(float x) {
    uint32_t u;
    asm("cvt.rna.tf32.f32 %0, %1;" : "=r"(u) : "f"(x));
    return __uint_as_float(u);
}
__device__ __forceinline__ uint32_t tf32_bits(float x) {
    uint32_t u;
    asm("cvt.rna.tf32.f32 %0, %1;" : "=r"(u) : "f"(x));
    return u;
}
#define MMA_TF32(d, a, b) \
    asm volatile("mma.sync.aligned.m16n8k8.row.col.f32.tf32.tf32.f32 " \
        "{%0,%1,%2,%3}, {%4,%5,%6,%7}, {%8,%9}, {%0,%1,%2,%3};" \
        : "+f"((d)[0]), "+f"((d)[1]), "+f"((d)[2]), "+f"((d)[3]) \
        : "r"((a)[0]), "r"((a)[1]), "r"((a)[2]), "r"((a)[3]), "r"((b)[0]), "r"((b)[1]))

// ---------------------------------------------------------------
__global__ void sht_init_trig() {
    int idx = blockIdx.x * blockDim.x + threadIdx.x;
    if (idx >= K2P * K2P) return;
    int k = idx / K2P;
    int j = idx - k * K2P;
    const double scale = 6.283185307179586476925286766559 / (double)NLON;
    float ve = 0.f, vo = 0.f;
    if (k <= 180) {
        if (j <= 180) {
            int r = (k * (2 * j)) % NLON;
            ve = (float)(cos(6.283185307179586476925286766559 * (double)r / (double)NLON) * scale);
        }
        if (j <= 179) {
            int r = (k * (2 * j + 1)) % NLON;
            vo = (float)(cos(6.283185307179586476925286766559 * (double)r / (double)NLON) * scale);
        }
    }
    sht_te[idx] = tf32_round(ve);
    sht_to[idx] = tf32_round(vo);
}

// ---------------------------------------------------------------
__global__ __launch_bounds__(256) void sht_fold(const float* __restrict__ x,
                                                unsigned xbud) {
    __shared__ float xs[16][720];
    const int row0 = blockIdx.x * 16;
    const int tid  = threadIdx.x;

    for (int i = tid; i < 16 * 720; i += 256) {
        int rl = i / 720, n = i - (i / 720) * 720;
        unsigned gi = (unsigned)(row0 + rl) * NLON + (unsigned)n;
        xs[rl][n] = (gi < xbud) ? x[gi] : 0.f;
    }
    __syncthreads();

    const int rl = tid & 15;
#pragma unroll
    for (int it = 0; it < 12; it++) {
        int n = (tid >> 4) + 16 * it;
        float ve = 0.f, vo = 0.f;
        if (n == 0) {
            float a0 = xs[rl][0], a1 = xs[rl][360];
            ve = a0 + a1; vo = a0 - a1;
        } else if (n <= 179) {
            float s1 = xs[rl][n] + xs[rl][720 - n];
            float s2 = xs[rl][360 - n] + xs[rl][360 + n];
            ve = s1 + s2; vo = s1 - s2;
        } else if (n == 180) {
            float s = xs[rl][180] + xs[rl][540];
            ve = s; vo = s;
        }
        size_t o = (size_t)n * NROWS + row0 + rl;
        sht_ye[o] = tf32_round(ve);
        sht_yo[o] = tf32_round(vo);
    }
}

// ---------------------------------------------------------------
// Stage 1 (tensor): 128 r x 128 j per block, K=192, [k][*] smem.
// grid=(361,4): p=by>>1, j0=(by&1)*64.
// ---------------------------------------------------------------
__global__ __launch_bounds__(256, 2) void sht_stage1() {
    __shared__ __align__(16) float As[2][16][SPITCH];
    __shared__ __align__(16) float Bs[2][16][SPITCH];

    const int tid  = threadIdx.x;
    const int row0 = blockIdx.x * 128;
    const int p    = blockIdx.y >> 1;
    const int j0   = (blockIdx.y & 1) * 64;
    const int wid  = tid >> 5;
    const int lane = tid & 31;
    const int wm   = wid & 3;
    const int wn   = wid >> 2;
    const int lr   = lane >> 2;
    const int lk   = lane & 3;

    const float* __restrict__ ya = p ? sht_yo : sht_ye;
    const float* __restrict__ tb = p ? sht_to : sht_te;

    const uint32_t sAs = (uint32_t)__cvta_generic_to_shared(&As[0][0][0]);
    const uint32_t sBs = (uint32_t)__cvta_generic_to_shared(&Bs[0][0][0]);

    float d[2][8][4];
#pragma unroll
    for (int g = 0; g < 2; g++)
#pragma unroll
        for (int n = 0; n < 8; n++)
#pragma unroll
            for (int i = 0; i < 4; i++) d[g][n][i] = 0.f;

#define S1_LOAD(buf, kb) do {                                                  \
        _Pragma("unroll")                                                      \
        for (int i = 0; i < 2; i++) {                                          \
            int f  = tid + i * 256;                                            \
            int kk = f >> 5;                                                   \
            int c4 = (f & 31) * 4;                                             \
            CP_ASYNC16(sAs + (uint32_t)((((buf)*16 + kk)*SPITCH + c4) * 4),    \
                       ya + (size_t)((kb) + kk) * NROWS + row0 + c4);          \
            CP_ASYNC16(sBs + (uint32_t)((((buf)*16 + kk)*SPITCH + c4) * 4),    \
                       tb + ((kb) + kk) * K2P + j0 + c4);                      \
        }                                                                      \
        CP_COMMIT();                                                           \
    } while (0)

    S1_LOAD(0, 0);

    for (int t = 0; t < NT1; t++) {
        if (t + 1 < NT1) { S1_LOAD((t + 1) & 1, 16 * (t + 1)); CP_WAIT1(); }
        else             { CP_WAIT0(); }
        __syncthreads();
        const int cb = t & 1;
#pragma unroll
        for (int kc = 0; kc < 16; kc += 8) {
            uint32_t a[2][4];
#pragma unroll
            for (int g = 0; g < 2; g++) {
                int rb = wm * 32 + g * 16 + lr;
                a[g][0] = __float_as_uint(As[cb][kc + lk][rb]);
                a[g][1] = __float_as_uint(As[cb][kc + lk][rb + 8]);
                a[g][2] = __float_as_uint(As[cb][kc + 4 + lk][rb]);
                a[g][3] = __float_as_uint(As[cb][kc + 4 + lk][rb + 8]);
            }
#pragma unroll
            for (int n = 0; n < 8; n++) {
                int cc = wn * 64 + n * 8 + lr;
                uint32_t b[2];
                b[0] = __float_as_uint(Bs[cb][kc + lk][cc]);
                b[1] = __float_as_uint(Bs[cb][kc + 4 + lk][cc]);
#pragma unroll
                for (int g = 0; g < 2; g++) MMA_TF32(d[g][n], a[g], b);
            }
        }
        __syncthreads();
    }
#undef S1_LOAD

    // Store tf32-rounded xfr[m][bc][k]; m = 2*(j0+jj)+p
#pragma unroll
    for (int g = 0; g < 2; g++) {
#pragma unroll
        for (int n = 0; n < 8; n++) {
#pragma unroll
            for (int e = 0; e < 4; e++) {
                int r  = row0 + wm * 32 + g * 16 + lr + ((e >> 1) << 3);
                int jj = wn * 64 + n * 8 + 2 * lk + (e & 1);
                int m  = 2 * (j0 + jj) + p;
                if (m > 360) continue;
                int bc = r / NLAT;
                int k  = r - bc * NLAT;
                sht_xfr[(size_t)m * BC * K1P + (size_t)bc * K1P + k] =
                    tf32_round(d[g][n][e]);
            }
        }
    }
}

// ---------------------------------------------------------------
// Stage 2 (tensor): s2[m][bc][l] = sum_k xfr[m][bc][k] * w[m][l][k]
// A-tiles [bc][k] pitch-20, 16B cp.async.
// W-tiles [l][k] pitch-20: ALIGNED-WINDOW 16B cp.async. Row source
// ro = ll*361+kb is 4B-aligned; load from ro&~3 (16B-aligned), 5x16B
// covering the 20-float window; fragments read with shift sh = cc&3.
// Front garbage (<sh) never read; k>=NLAT garbage killed by A k-pad
// zeros; buffer-end overrun falls back to guarded scalar loads.
// 128x128, K=368. grid=(3,361).
// ---------------------------------------------------------------
__global__ __launch_bounds__(256, 2) void sht_stage2(const float* __restrict__ w,
                                                     unsigned wbud) {
    __shared__ __align__(16) float As[2][128][APITCH];
    __shared__ __align__(16) float Ws[2][128][APITCH];

    const int tid = threadIdx.x;
    const int m   = blockIdx.y;
    const int l0  = blockIdx.x * 128;
    const int wid  = tid >> 5;
    const int lane = tid & 31;
    const int wm   = wid & 3;
    const int wn   = wid >> 2;
    const int lr   = lane >> 2;
    const int lk   = lane & 3;

    const float* __restrict__ xa = sht_xfr + (size_t)m * BC * K1P;
    const float* __restrict__ wp = w + (size_t)m * (LMAX * NLAT);
    const unsigned wrow_max = (wbud > (unsigned)((size_t)m * (LMAX * NLAT)))
                            ? (unsigned)(wbud - (size_t)m * (LMAX * NLAT)) : 0u;

    const uint32_t sAs = (uint32_t)__cvta_generic_to_shared(&As[0][0][0]);
    const uint32_t sWs = (uint32_t)__cvta_generic_to_shared(&Ws[0][0][0]);

    float d[2][8][4];
#pragma unroll
    for (int g = 0; g < 2; g++)
#pragma unroll
        for (int n = 0; n < 8; n++)
#pragma unroll
            for (int i = 0; i < 4; i++) d[g][n][i] = 0.f;

#define S2_LOAD(buf, kb) do {                                                  \
        _Pragma("unroll")                                                      \
        for (int i = 0; i < 2; i++) {                                          \
            int f   = tid + i * 256;                                           \
            int bcr = f >> 2;                                                  \
            int c4  = (f & 3) * 4;                                             \
            CP_ASYNC16(sAs + (uint32_t)((((buf)*128 + bcr)*APITCH + c4) * 4),  \
                       xa + (size_t)bcr * K1P + (kb) + c4);                    \
        }                                                                      \
        _Pragma("unroll")                                                      \
        for (int i = 0; i < 3; i++) {                                          \
            int idx = tid + i * 256;                                           \
            if (idx < 640) {                                                   \
                int lrw  = idx & 127;                                          \
                int part = idx >> 7;        /* 0..4 */                         \
                int ll   = l0 + lrw;                                           \
                if (ll < LMAX) {                                               \
                    unsigned ro   = (unsigned)ll * NLAT + (unsigned)(kb);      \
                    unsigned src  = (ro & ~3u) + (unsigned)(part * 4);         \
                    uint32_t ds = sWs + (uint32_t)((((buf)*128 + lrw)*APITCH + part*4) * 4); \
                    if (src + 4u <= wrow_max) {                                \
                        CP_ASYNC16(ds, wp + src);                              \
                    } else {                                                   \
                        _Pragma("unroll")                                      \
                        for (int q = 0; q < 4; q++) {                          \
                            if (src + (unsigned)q < wrow_max)                  \
                                CP_ASYNC4(ds + (uint32_t)(q * 4), wp + src + q); \
                            else                                               \
                                Ws[buf][lrw][part*4 + q] = 0.f;                \
                        }                                                      \
                    }                                                          \
                }                                                              \
            }                                                                  \
        }                                                                      \
        CP_COMMIT();                                                           \
    } while (0)

    S2_LOAD(0, 0);

    for (int t = 0; t < NT2; t++) {
        if (t + 1 < NT2) { S2_LOAD((t + 1) & 1, 16 * (t + 1)); CP_WAIT1(); }
        else             { CP_WAIT0(); }
        __syncthreads();
        const int cb = t & 1;
#pragma unroll
        for (int kc = 0; kc < 16; kc += 8) {
            uint32_t a[2][4];
#pragma unroll
            for (int g = 0; g < 2; g++) {
                int rb = wm * 32 + g * 16 + lr;
                a[g][0] = __float_as_uint(As[cb][rb][kc + lk]);
                a[g][1] = __float_as_uint(As[cb][rb + 8][kc + lk]);
                a[g][2] = __float_as_uint(As[cb][rb][kc + 4 + lk]);
                a[g][3] = __float_as_uint(As[cb][rb + 8][kc + 4 + lk]);
            }
#pragma unroll
            for (int n = 0; n < 8; n++) {
                int cc = wn * 64 + n * 8 + lr;
                int sh = cc & 3;    // window shift for this l-row
                uint32_t b[2];
                b[0] = tf32_bits(Ws[cb][cc][sh + kc + lk]);
                b[1] = tf32_bits(Ws[cb][cc][sh + kc + 4 + lk]);
#pragma unroll
                for (int g = 0; g < 2; g++) MMA_TF32(d[g][n], a[g], b);
            }
        }
        __syncthreads();
    }
#undef S2_LOAD

    // Coalesced float2 store to s2[m][bc][l]
    const size_t sb = (size_t)m * (BC * LPAD);
#pragma unroll
    for (int g = 0; g < 2; g++) {
#pragma unroll
        for (int n = 0; n < 8; n++) {
            int bc0 = wm * 32 + g * 16 + lr;
            int l   = l0 + wn * 64 + n * 8 + 2 * lk;
            *(float2*)&sht_s2[sb + (size_t)bc0 * LPAD + l] =
                make_float2(d[g][n][0], d[g][n][1]);
            *(float2*)&sht_s2[sb + (size_t)(bc0 + 8) * LPAD + l] =
                make_float2(d[g][n][2], d[g][n][3]);
        }
    }
}

// ---------------------------------------------------------------
// Output transpose: s2[m][bc][l] -> out[(bc*360+l)*361+m]
// 4 bc per block.  grid=(12 lt, 12 mt, 32), block=(32,8)
// ---------------------------------------------------------------
__global__ void sht_xpose_out(float* __restrict__ out, unsigned obud) {
    __shared__ float t[32][33];
    const int l0 = blockIdx.x * 32;
    const int m0 = blockIdx.y * 32;

    for (int bz = 0; bz < 4; bz++) {
        const int bc = blockIdx.z * 4 + bz;
        for (int i = threadIdx.y; i < 32; i += 8) {
            int m = m0 + i;
            float v = 0.f;
            if (m < MMAX)
                v = sht_s2[(size_t)m * (BC * LPAD) + (size_t)bc * LPAD + l0 + threadIdx.x];
            t[i][threadIdx.x] = v;
        }
        __syncthreads();
        for (int i = threadIdx.y; i < 32; i += 8) {
            int l = l0 + i;
            int m = m0 + threadIdx.x;
            if (l < LMAX && m < MMAX) {
                unsigned ci = ((unsigned)bc * LMAX + (unsigned)l) * MMAX + (unsigned)m;
                if (ci < obud) out[ci] = t[threadIdx.x][i];
            }
        }
        __syncthreads();
    }
}

// ---------------------------------------------------------------
extern "C" void kernel_launch(void* const* d_in, const int* in_sizes, int n_in,
                              void* d_out, int out_size) {
    const float* x = nullptr;
    const float* w = nullptr;
    unsigned xbud = 0, wbud = 0;

    for (int i = 0; i < n_in; i++) {
        if (in_sizes[i] == X_ELEMS && !x) { x = (const float*)d_in[i]; xbud = X_ELEMS; }
        else if (in_sizes[i] == W_ELEMS && !w) { w = (const float*)d_in[i]; wbud = W_ELEMS; }
    }
    if (!x && n_in >= 1) {
        x = (const float*)d_in[0];
        long s = in_sizes[0];
        xbud = (unsigned)((s > 0 && s < (long)X_ELEMS) ? s : X_ELEMS);
    }
    if (!w && n_in >= 2) {
        w = (const float*)d_in[1];
        long s = in_sizes[1];
        wbud = (unsigned)((s > 0 && s < (long)W_ELEMS) ? s : W_ELEMS);
    }

    unsigned obud;
    if (out_size <= 0) obud = OUT_REAL;
    else obud = ((unsigned)out_size < (unsigned)OUT_REAL) ? (unsigned)out_size
                                                          : (unsigned)OUT_REAL;

    float* out = (float*)d_out;

    sht_init_trig<<<(K2P * K2P + 255) / 256, 256>>>();
    sht_fold<<<NROWS / 16, 256>>>(x, xbud);
    sht_stage1<<<dim3(361, 4), 256>>>();
    sht_stage2<<<dim3(3, MMAX), 256>>>(w, wbud);
    sht_xpose_out<<<dim3(12, 12, 32), dim3(32, 8)>>>(out, obud);
}

// round 16
// speedup vs baseline: 1.1530x; 1.1530x over previous
#include <cuda_runtime.h>
#include <math.h>
#include <stdint.h>

// Problem constants
#define NLAT 361
#define NLON 720
#define MMAX 361
#define LMAX 360
#define BC   128
#define NROWS (BC * NLAT)   // 46208

#define X_ELEMS  (BC * NLAT * NLON)
#define W_ELEMS  (MMAX * LMAX * NLAT)
#define OUT_REAL (BC * LMAX * MMAX)

#define K1P 368             // latitude K padded (stage-2)
#define K2P 192             // folded DFT K padded (stage-1)
#define NT1 (K2P / 16)      // 12
#define NT2 (K1P / 16)      // 23
#define LPAD 384
#define APITCH 20           // smem pitch for [row][k] tiles (conflict-free)

// -------- static device scratch (zero-initialized at load) --------
__device__ float sht_te[K2P * K2P];                // [j][k] even-m trig
__device__ float sht_to[K2P * K2P];                // [j][k] odd-m trig
__device__ float sht_ye[(size_t)NROWS * K2P];      // [r][k] even fold
__device__ float sht_yo[(size_t)NROWS * K2P];      // [r][k] odd fold
__device__ float sht_xfr[(size_t)MMAX * BC * K1P]; // [m][bc][k], tf32, k-pad 0
__device__ float sht_s2[(size_t)MMAX * BC * LPAD]; // [m][bc][l]

#define CP_ASYNC16(s, g) asm volatile("cp.async.ca.shared.global [%0], [%1], 16;" :: "r"(s), "l"(g) : "memory")
#define CP_ASYNC4(s, g)  asm volatile("cp.async.ca.shared.global [%0], [%1], 4;"  :: "r"(s), "l"(g) : "memory")
#define CP_COMMIT()      asm volatile("cp.async.commit_group;" ::: "memory")
#define CP_WAIT1()       asm volatile("cp.async.wait_group 1;" ::: "memory")
#define CP_WAIT0()       asm volatile("cp.async.wait_group 0;" ::: "memory")

__device__ __forceinline__ float tf32_round(float x) {
    uint32_t u;
    asm("cvt.rna.tf32.f32 %0, %1;" : "=r"(u) : "f"(x));
    return __uint_as_float(u);
}
__device__ __forceinline__ uint32_t tf32_bits(float x) {
    uint32_t u;
    asm("cvt.rna.tf32.f32 %0, %1;" : "=r"(u) : "f"(x));
    return u;
}
#define MMA_TF32(d, a, b) \
    asm volatile("mma.sync.aligned.m16n8k8.row.col.f32.tf32.tf32.f32 " \
        "{%0,%1,%2,%3}, {%4,%5,%6,%7}, {%8,%9}, {%0,%1,%2,%3};" \
        : "+f"((d)[0]), "+f"((d)[1]), "+f"((d)[2]), "+f"((d)[3]) \
        : "r"((a)[0]), "r"((a)[1]), "r"((a)[2]), "r"((a)[3]), "r"((b)[0]), "r"((b)[1]))

// ---------------------------------------------------------------
// Trig tables [j][k]: te = cos(2pi*k*(2j)/720)*s, to = cos(2pi*k*(2j+1)/720)*s
// ---------------------------------------------------------------
__global__ void sht_init_trig() {
    int idx = blockIdx.x * blockDim.x + threadIdx.x;
    if (idx >= K2P * K2P) return;
    int j = idx / K2P;
    int k = idx - j * K2P;
    const double scale = 6.283185307179586476925286766559 / (double)NLON;
    float ve = 0.f, vo = 0.f;
    if (k <= 180) {
        if (j <= 180) {
            int r = (k * (2 * j)) % NLON;
            ve = (float)(cos(6.283185307179586476925286766559 * (double)r / (double)NLON) * scale);
        }
        if (j <= 179) {
            int r = (k * (2 * j + 1)) % NLON;
            vo = (float)(cos(6.283185307179586476925286766559 * (double)r / (double)NLON) * scale);
        }
    }
    sht_te[idx] = tf32_round(ve);
    sht_to[idx] = tf32_round(vo);
}

// ---------------------------------------------------------------
// Fold, row-major output: ye/yo[r][n], n in [0,191] (pad zero).
// ---------------------------------------------------------------
__global__ __launch_bounds__(256) void sht_fold(const float* __restrict__ x,
                                                unsigned xbud) {
    __shared__ float xs[16][720];
    const int row0 = blockIdx.x * 16;
    const int tid  = threadIdx.x;

    for (int i = tid; i < 16 * 720; i += 256) {
        int rl = i / 720, n = i - (i / 720) * 720;
        unsigned gi = (unsigned)(row0 + rl) * NLON + (unsigned)n;
        xs[rl][n] = (gi < xbud) ? x[gi] : 0.f;
    }
    __syncthreads();

    const int rl = tid >> 4;       // 0..15
    const int n0 = tid & 15;
    const size_t rb = (size_t)(row0 + rl) * K2P;
#pragma unroll
    for (int it = 0; it < 12; it++) {
        int n = n0 + 16 * it;      // 0..191
        float ve = 0.f, vo = 0.f;
        if (n == 0) {
            float a0 = xs[rl][0], a1 = xs[rl][360];
            ve = a0 + a1; vo = a0 - a1;
        } else if (n <= 179) {
            float s1 = xs[rl][n] + xs[rl][720 - n];
            float s2 = xs[rl][360 - n] + xs[rl][360 + n];
            ve = s1 + s2; vo = s1 - s2;
        } else if (n == 180) {
            float s = xs[rl][180] + xs[rl][540];
            ve = s; vo = s;
        }
        sht_ye[rb + n] = tf32_round(ve);
        sht_yo[rb + n] = tf32_round(vo);
    }
}

// ---------------------------------------------------------------
// Stage 1 (tensor): 128 r x 128 j per block, K=192.
// Both operands [row][k] pitch-20 smem (conflict-free fragments).
// grid=(361,4): p=by>>1, j0=(by&1)*64.
// ---------------------------------------------------------------
__global__ __launch_bounds__(256, 2) void sht_stage1() {
    __shared__ __align__(16) float As[2][128][APITCH];
    __shared__ __align__(16) float Bs[2][128][APITCH];

    const int tid  = threadIdx.x;
    const int row0 = blockIdx.x * 128;
    const int p    = blockIdx.y >> 1;
    const int j0   = (blockIdx.y & 1) * 64;
    const int wid  = tid >> 5;
    const int lane = tid & 31;
    const int wm   = wid & 3;
    const int wn   = wid >> 2;
    const int lr   = lane >> 2;
    const int lk   = lane & 3;

    const float* __restrict__ ya = p ? sht_yo : sht_ye;
    const float* __restrict__ tb = p ? sht_to : sht_te;

    const uint32_t sAs = (uint32_t)__cvta_generic_to_shared(&As[0][0][0]);
    const uint32_t sBs = (uint32_t)__cvta_generic_to_shared(&Bs[0][0][0]);

    float d[2][8][4];
#pragma unroll
    for (int g = 0; g < 2; g++)
#pragma unroll
        for (int n = 0; n < 8; n++)
#pragma unroll
            for (int i = 0; i < 4; i++) d[g][n][i] = 0.f;

#define S1_LOAD(buf, kb) do {                                                  \
        _Pragma("unroll")                                                      \
        for (int i = 0; i < 2; i++) {                                          \
            int f   = tid + i * 256;                                           \
            int row = f >> 2;                                                  \
            int c4  = (f & 3) * 4;                                             \
            CP_ASYNC16(sAs + (uint32_t)((((buf)*128 + row)*APITCH + c4) * 4),  \
                       ya + (size_t)(row0 + row) * K2P + (kb) + c4);           \
            CP_ASYNC16(sBs + (uint32_t)((((buf)*128 + row)*APITCH + c4) * 4),  \
                       tb + (size_t)(j0 + row) * K2P + (kb) + c4);             \
        }                                                                      \
        CP_COMMIT();                                                           \
    } while (0)

    S1_LOAD(0, 0);

    for (int t = 0; t < NT1; t++) {
        if (t + 1 < NT1) { S1_LOAD((t + 1) & 1, 16 * (t + 1)); CP_WAIT1(); }
        else             { CP_WAIT0(); }
        __syncthreads();
        const int cb = t & 1;
#pragma unroll
        for (int kc = 0; kc < 16; kc += 8) {
            uint32_t a[2][4];
#pragma unroll
            for (int g = 0; g < 2; g++) {
                int rb = wm * 32 + g * 16 + lr;
                a[g][0] = __float_as_uint(As[cb][rb][kc + lk]);
                a[g][1] = __float_as_uint(As[cb][rb + 8][kc + lk]);
                a[g][2] = __float_as_uint(As[cb][rb][kc + 4 + lk]);
                a[g][3] = __float_as_uint(As[cb][rb + 8][kc + 4 + lk]);
            }
#pragma unroll
            for (int n = 0; n < 8; n++) {
                int cc = wn * 64 + n * 8 + lr;
                uint32_t b[2];
                b[0] = __float_as_uint(Bs[cb][cc][kc + lk]);
                b[1] = __float_as_uint(Bs[cb][cc][kc + 4 + lk]);
#pragma unroll
                for (int g = 0; g < 2; g++) MMA_TF32(d[g][n], a[g], b);
            }
        }
        __syncthreads();
    }
#undef S1_LOAD

    // Store tf32-rounded xfr[m][bc][k]; m = 2*(j0+jj)+p
#pragma unroll
    for (int g = 0; g < 2; g++) {
#pragma unroll
        for (int n = 0; n < 8; n++) {
#pragma unroll
            for (int e = 0; e < 4; e++) {
                int r  = row0 + wm * 32 + g * 16 + lr + ((e >> 1) << 3);
                int jj = wn * 64 + n * 8 + 2 * lk + (e & 1);
                int m  = 2 * (j0 + jj) + p;
                if (m > 360) continue;
                int bc = r / NLAT;
                int k  = r - bc * NLAT;
                sht_xfr[(size_t)m * BC * K1P + (size_t)bc * K1P + k] =
                    tf32_round(d[g][n][e]);
            }
        }
    }
}

// ---------------------------------------------------------------
// Stage 2 (tensor) — exact R14 form (proven 131us).
// A-tiles [bc][k] pitch-20, 16B cp.async; W-tiles [l][k] pitch-20,
// guarded 4B cp.async (W row stride 1444B not 16B-aligned).
// 128x128, K=368. grid=(3,361).
// ---------------------------------------------------------------
__global__ __launch_bounds__(256, 2) void sht_stage2(const float* __restrict__ w,
                                                     unsigned wbud) {
    __shared__ __align__(16) float As[2][128][APITCH];
    __shared__ __align__(16) float Ws[2][128][APITCH];

    const int tid = threadIdx.x;
    const int m   = blockIdx.y;
    const int l0  = blockIdx.x * 128;
    const int wid  = tid >> 5;
    const int lane = tid & 31;
    const int wm   = wid & 3;
    const int wn   = wid >> 2;
    const int lr   = lane >> 2;
    const int lk   = lane & 3;

    const float* __restrict__ xa = sht_xfr + (size_t)m * BC * K1P;
    const float* __restrict__ wp = w + (size_t)m * (LMAX * NLAT);
    const unsigned wrow_max = (wbud > (unsigned)((size_t)m * (LMAX * NLAT)))
                            ? (unsigned)(wbud - (size_t)m * (LMAX * NLAT)) : 0u;

    const uint32_t sAs = (uint32_t)__cvta_generic_to_shared(&As[0][0][0]);
    const uint32_t sWs = (uint32_t)__cvta_generic_to_shared(&Ws[0][0][0]);

    float d[2][8][4];
#pragma unroll
    for (int g = 0; g < 2; g++)
#pragma unroll
        for (int n = 0; n < 8; n++)
#pragma unroll
            for (int i = 0; i < 4; i++) d[g][n][i] = 0.f;

#define S2_LOAD(buf, kb) do {                                                  \
        _Pragma("unroll")                                                      \
        for (int i = 0; i < 2; i++) {                                          \
            int f   = tid + i * 256;                                           \
            int bcr = f >> 2;                                                  \
            int c4  = (f & 3) * 4;                                             \
            CP_ASYNC16(sAs + (uint32_t)((((buf)*128 + bcr)*APITCH + c4) * 4),  \
                       xa + (size_t)bcr * K1P + (kb) + c4);                    \
        }                                                                      \
        _Pragma("unroll")                                                      \
        for (int i = 0; i < 8; i++) {                                          \
            int f   = tid + i * 256;                                           \
            int lrw = f >> 4;                                                  \
            int kk  = f & 15;                                                  \
            int k   = (kb) + kk;                                               \
            int ll  = l0 + lrw;                                                \
            uint32_t ds = sWs + (uint32_t)((((buf)*128 + lrw)*APITCH + kk) * 4); \
            unsigned ro = (unsigned)ll * NLAT + (unsigned)k;                   \
            if (ll < LMAX && k < NLAT && ro < wrow_max)                        \
                CP_ASYNC4(ds, wp + ro);                                        \
            else                                                               \
                Ws[buf][lrw][kk] = 0.f;                                        \
        }                                                                      \
        CP_COMMIT();                                                           \
    } while (0)

    S2_LOAD(0, 0);

    for (int t = 0; t < NT2; t++) {
        if (t + 1 < NT2) { S2_LOAD((t + 1) & 1, 16 * (t + 1)); CP_WAIT1(); }
        else             { CP_WAIT0(); }
        __syncthreads();
        const int cb = t & 1;
#pragma unroll
        for (int kc = 0; kc < 16; kc += 8) {
            uint32_t a[2][4];
#pragma unroll
            for (int g = 0; g < 2; g++) {
                int rb = wm * 32 + g * 16 + lr;
                a[g][0] = __float_as_uint(As[cb][rb][kc + lk]);
                a[g][1] = __float_as_uint(As[cb][rb + 8][kc + lk]);
                a[g][2] = __float_as_uint(As[cb][rb][kc + 4 + lk]);
                a[g][3] = __float_as_uint(As[cb][rb + 8][kc + 4 + lk]);
            }
#pragma unroll
            for (int n = 0; n < 8; n++) {
                int cc = wn * 64 + n * 8 + lr;
                uint32_t b[2];
                b[0] = tf32_bits(Ws[cb][cc][kc + lk]);
                b[1] = tf32_bits(Ws[cb][cc][kc + 4 + lk]);
#pragma unroll
                for (int g = 0; g < 2; g++) MMA_TF32(d[g][n], a[g], b);
            }
        }
        __syncthreads();
    }
#undef S2_LOAD

    // Coalesced float2 store to s2[m][bc][l]
    const size_t sb = (size_t)m * (BC * LPAD);
#pragma unroll
    for (int g = 0; g < 2; g++) {
#pragma unroll
        for (int n = 0; n < 8; n++) {
            int bc0 = wm * 32 + g * 16 + lr;
            int l   = l0 + wn * 64 + n * 8 + 2 * lk;
            *(float2*)&sht_s2[sb + (size_t)bc0 * LPAD + l] =
                make_float2(d[g][n][0], d[g][n][1]);
            *(float2*)&sht_s2[sb + (size_t)(bc0 + 8) * LPAD + l] =
                make_float2(d[g][n][2], d[g][n][3]);
        }
    }
}

// ---------------------------------------------------------------
// Output transpose: s2[m][bc][l] -> out[(bc*360+l)*361+m]
// 4 bc per block.  grid=(12 lt, 12 mt, 32), block=(32,8)
// ---------------------------------------------------------------
__global__ void sht_xpose_out(float* __restrict__ out, unsigned obud) {
    __shared__ float t[32][33];
    const int l0 = blockIdx.x * 32;
    const int m0 = blockIdx.y * 32;

    for (int bz = 0; bz < 4; bz++) {
        const int bc = blockIdx.z * 4 + bz;
        for (int i = threadIdx.y; i < 32; i += 8) {
            int m = m0 + i;
            float v = 0.f;
            if (m < MMAX)
                v = sht_s2[(size_t)m * (BC * LPAD) + (size_t)bc * LPAD + l0 + threadIdx.x];
            t[i][threadIdx.x] = v;
        }
        __syncthreads();
        for (int i = threadIdx.y; i < 32; i += 8) {
            int l = l0 + i;
            int m = m0 + threadIdx.x;
            if (l < LMAX && m < MMAX) {
                unsigned ci = ((unsigned)bc * LMAX + (unsigned)l) * MMAX + (unsigned)m;
                if (ci < obud) out[ci] = t[threadIdx.x][i];
            }
        }
        __syncthreads();
    }
}

// ---------------------------------------------------------------
extern "C" void kernel_launch(void* const* d_in, const int* in_sizes, int n_in,
                              void* d_out, int out_size) {
    const float* x = nullptr;
    const float* w = nullptr;
    unsigned xbud = 0, wbud = 0;

    for (int i = 0; i < n_in; i++) {
        if (in_sizes[i] == X_ELEMS && !x) { x = (const float*)d_in[i]; xbud = X_ELEMS; }
        else if (in_sizes[i] == W_ELEMS && !w) { w = (const float*)d_in[i]; wbud = W_ELEMS; }
    }
    if (!x && n_in >= 1) {
        x = (const float*)d_in[0];
        long s = in_sizes[0];
        xbud = (unsigned)((s > 0 && s < (long)X_ELEMS) ? s : X_ELEMS);
    }
    if (!w && n_in >= 2) {
        w = (const float*)d_in[1];
        long s = in_sizes[1];
        wbud = (unsigned)((s > 0 && s < (long)W_ELEMS) ? s : W_ELEMS);
    }

    unsigned obud;
    if (out_size <= 0) obud = OUT_REAL;
    else obud = ((unsigned)out_size < (unsigned)OUT_REAL) ? (unsigned)out_size
                                                          : (unsigned)OUT_REAL;

    float* out = (float*)d_out;

    sht_init_trig<<<(K2P * K2P + 255) / 256, 256>>>();
    sht_fold<<<NROWS / 16, 256>>>(x, xbud);
    sht_stage1<<<dim3(361, 4), 256>>>();
    sht_stage2<<<dim3(3, MMAX), 256>>>(w, wbud);
    sht_xpose_out<<<dim3(12, 12, 32), dim3(32, 8)>>>(out, obud);
}